// round 14
// baseline (speedup 1.0000x reference)
#include <cuda_runtime.h>
#include <math.h>

#define H 32
#define F 8
#define TCH 32
#define NWARP 4
#define SEG (TCH / NWARP)    // 8
#define NTHR (NWARP * 32)    // 128
#define FULL 0xffffffffu
#define BMAX 512

typedef unsigned long long ull;

__device__ float g_wX[4 * F * H];
__device__ float g_bias[4 * H];
__device__ float g_A[2 * H];
__device__ float2 g_A2X2[2][BMAX * H];   // block-2 half transforms
__device__ float  g_hlast[BMAX * H];
__device__ int    g_done[BMAX];

struct SmemLayout {
    float4 xs[2][TCH * F / 4];   // 2KB
    float2 cEU[TCH * H];         // 8KB
    float  cV[TCH * H];          // 4KB
    float2 segAX[2][NWARP * H];  // 2KB (double-buffered: lite loop uses 1 bar/chunk)
    float2 seg2[2][NWARP * H];   // 2KB
    float2 swp01[F * H];         // 2KB
    float2 swp23[F * H];         // 2KB
    float2 swd2p[(H / 2) * H];   // 4KB
    float  sbias[4 * H];
    float  sA[2 * H];
    int    sdone;
};

__device__ __forceinline__ float ex2f(float x) { float r; asm("ex2.approx.f32 %0,%1;" : "=f"(r) : "f"(x)); return r; }
__device__ __forceinline__ float lg2f(float x) { float r; asm("lg2.approx.f32 %0,%1;" : "=f"(r) : "f"(x)); return r; }
__device__ __forceinline__ float tanh_f(float x) { float r; asm("tanh.approx.f32 %0,%1;" : "=f"(r) : "f"(x)); return r; }

__device__ __forceinline__ ull pack2(float lo, float hi) {
    ull r; asm("mov.b64 %0, {%1, %2};" : "=l"(r) : "r"(__float_as_uint(lo)), "r"(__float_as_uint(hi)));
    return r;
}
__device__ __forceinline__ ull splat2(float x) {
    ull r; asm("mov.b64 %0, {%1, %1};" : "=l"(r) : "r"(__float_as_uint(x)));
    return r;
}
__device__ __forceinline__ float2 unpack2(ull v) {
    unsigned lo, hi; asm("mov.b64 {%0, %1}, %2;" : "=r"(lo), "=r"(hi) : "l"(v));
    return make_float2(__uint_as_float(lo), __uint_as_float(hi));
}
__device__ __forceinline__ void fma2(ull& d, ull a, ull b) {
    asm("fma.rn.f32x2 %0, %1, %2, %0;" : "+l"(d) : "l"(a), "l"(b));
}

__device__ __forceinline__ void splus_decay(float u, float A, float& d, float& a) {
    const float L2E = 1.4426950408889634f;
    const float LN2 = 0.6931471805599453f;
    float p = ex2f(-fabsf(u) * L2E);
    float q = lg2f(1.f + p);
    float r = fmaf(fmaxf(u, 0.f), L2E, q);
    d = r * LN2;
    a = ex2f(-A * r);
}

__device__ __forceinline__ float sigmoid_f(float u) {
    return fmaf(tanh_f(0.5f * u), 0.5f, 0.5f);
}

__device__ __forceinline__ float gelu_f(float u) {
    float inner = 0.7978845608028654f * fmaf(0.044715f * u, u * u, u);
    float ex = ex2f(2.f * inner * 1.4426950408889634f);
    float th = 1.f - __fdividef(2.f, ex + 1.f);
    return 0.5f * u * (1.f + th);
}

__device__ __forceinline__ float warp_allsum(float v) {
    #pragma unroll
    for (int off = 16; off; off >>= 1) v += __shfl_xor_sync(FULL, v, off);
    return v;
}

__global__ void setup_kernel(const float* __restrict__ We, const float* __restrict__ be,
                             const float* __restrict__ Wd, const float* __restrict__ bd,
                             const float* __restrict__ Alog, const float* __restrict__ Wg,
                             const float* __restrict__ bg) {
    int tid = threadIdx.x;
    for (int idx = tid; idx < F * H; idx += blockDim.x) g_wX[idx] = We[idx];
    for (int idx = tid; idx < 3 * F * H; idx += blockDim.x) {
        int m = idx / (F * H);
        int r = idx % (F * H);
        int f = r / H, k = r % H;
        const float* M = (m == 0) ? Wd : (m == 1) ? Wg : (Wd + H * H);
        float s = 0.f;
        for (int h = 0; h < H; h++) s += We[f * H + h] * M[h * H + k];
        g_wX[(m + 1) * F * H + r] = s;
    }
    for (int idx = tid; idx < 4 * H; idx += blockDim.x) {
        int m = idx / H, k = idx % H;
        float v;
        if (m == 0) v = be[k];
        else {
            const float* M; const float* bb;
            if (m == 1)      { M = Wd;         bb = bd;     }
            else if (m == 2) { M = Wg;         bb = bg;     }
            else             { M = Wd + H * H; bb = bd + H; }
            float s = 0.f;
            for (int h = 0; h < H; h++) s += be[h] * M[h * H + k];
            v = s + bb[k];
        }
        g_bias[idx] = v;
    }
    for (int idx = tid; idx < 2 * H; idx += blockDim.x) g_A[idx] = expf(Alog[idx]);
    for (int idx = tid; idx < BMAX; idx += blockDim.x) g_done[idx] = 0;
}

__global__ void __launch_bounds__(NTHR, 4)
forecast_kernel(const float* __restrict__ x, const float* __restrict__ Wd,
                const float* __restrict__ Wg, const float* __restrict__ bg,
                const float* __restrict__ gamma_, const float* __restrict__ beta_,
                const float* __restrict__ W1, const float* __restrict__ b1,
                const float* __restrict__ W2, const float* __restrict__ b2,
                float* __restrict__ out, int S) {
    extern __shared__ float smraw[];
    SmemLayout& sm = *reinterpret_cast<SmemLayout*>(smraw);
    const int tid  = threadIdx.x;
    const int lane = tid & 31;
    const int w    = tid >> 5;
    const int b    = blockIdx.x;
    const int q    = blockIdx.y;            // half index: 0 or 1
    const int hlen = S / 2;
    const long t0  = (long)b * S + (long)q * hlen;
    const int nchunk = hlen / TCH;

    // ---- stage weights into smem (paired layouts) ----
    for (int i = tid; i < F * H; i += NTHR) {
        int j = i / H, k = i % H;
        sm.swp01[i] = make_float2(g_wX[0 * F * H + j * H + k], g_wX[1 * F * H + j * H + k]);
        sm.swp23[i] = make_float2(g_wX[2 * F * H + j * H + k], g_wX[3 * F * H + j * H + k]);
    }
    for (int i = tid; i < (H / 2) * H; i += NTHR) {
        int p = i / H, k = i % H;
        sm.swd2p[i] = make_float2(Wd[H * H + (2 * p) * H + k], Wd[H * H + (2 * p + 1) * H + k]);
    }
    for (int i = tid; i < 4 * H; i += NTHR) sm.sbias[i] = g_bias[i];
    for (int i = tid; i < 2 * H; i += NTHR) sm.sA[i] = g_A[i];
    if (tid < NWARP * H) sm.seg2[1][tid] = make_float2(1.f, 0.f);
    // stage x chunk 0: half-1 CTAs start with the LITE region (front of sequence)
    {
        const long lt0 = (q == 1) ? (long)b * S : t0;
        if (tid < TCH * F / 4) {
            const float4* src = reinterpret_cast<const float4*>(x + lt0 * F);
            sm.xs[0][tid] = src[tid];
        }
    }
    __syncthreads();

    // ---- persistent register weights ----
    ull wp01[F], wp23[F];
    #pragma unroll
    for (int j = 0; j < F; j++) {
        float2 p0 = sm.swp01[j * H + lane];
        float2 p2 = sm.swp23[j * H + lane];
        wp01[j] = pack2(p0.x, p0.y);
        wp23[j] = pack2(p2.x, p2.y);
    }
    ull wd2p[H / 2];
    #pragma unroll
    for (int p = 0; p < H / 2; p++) {
        float2 wv = sm.swd2p[p * H + lane];
        wd2p[p] = pack2(wv.x, wv.y);
    }
    const ull bias01 = pack2(sm.sbias[lane],         sm.sbias[H + lane]);
    const ull bias23 = pack2(sm.sbias[2 * H + lane], sm.sbias[3 * H + lane]);
    const float A1k = sm.sA[lane];
    const float A2k = sm.sA[H + lane];

    float carry1 = 0.f;

    // ===== LITE PREFIX (half-1 CTAs only): block-1 state at S/2 =====
    if (q == 1) {
        const long lt0 = (long)b * S;
        for (int c = 0; c < nchunk; c++) {
            const int cb = c & 1;
            // prefetch next lite chunk (or, on last lite chunk, this half's first chunk)
            if (tid < TCH * F / 4) {
                const long nx = (c + 1 < nchunk) ? (lt0 + (c + 1) * TCH) : t0;
                const float4* src = reinterpret_cast<const float4*>(x + nx * F);
                sm.xs[cb ^ 1][tid] = src[tid];
            }
            float Aw = 1.f, Xw = 0.f;
            #pragma unroll
            for (int i = 0; i < SEG; i++) {
                const int t = w * SEG + i;
                float4 xa  = sm.xs[cb][t * 2];
                float4 xb4 = sm.xs[cb][t * 2 + 1];
                float xv[8] = {xa.x, xa.y, xa.z, xa.w, xb4.x, xb4.y, xb4.z, xb4.w};
                ull a01 = bias01;
                #pragma unroll
                for (int j = 0; j < F; j++) fma2(a01, splat2(xv[j]), wp01[j]);
                float2 eu1 = unpack2(a01);
                float d1, a1;
                splus_decay(eu1.y, A1k, d1, a1);
                Xw = fmaf(a1, Xw, d1 * eu1.x);
                Aw *= a1;
            }
            sm.segAX[cb][w * H + lane] = make_float2(Aw, Xw);
            __syncthreads();
            #pragma unroll
            for (int ww = 0; ww < NWARP; ww++) {
                float2 ax = sm.segAX[cb][ww * H + lane];
                carry1 = fmaf(ax.x, carry1, ax.y);
            }
        }
        // sm.xs[nchunk & 1] now holds this half's chunk 0 — matches main loop cb=0
        // only if nchunk is even; handle generically:
    }
    // ensure main-loop chunk 0 is in xs[0]
    {
        const int need = (q == 1) ? (nchunk & 1) : 0;
        if (need != 0) {
            // nchunk odd: chunk 0 of main loop landed in xs[1]; copy path unused
            // (nchunk = 2048/32 = 64, even — this branch never triggers for S=4096)
            __syncthreads();
            if (tid < TCH * F / 4) sm.xs[0][tid] = sm.xs[1][tid];
        }
    }
    __syncthreads();

    float cA2 = 1.f, cX2 = 0.f;

    // ===== MAIN HALF PIPELINE =====
    for (int c = 0; c < nchunk; c++) {
        const int cb = c & 1;
        float a1r[SEG], x1r[SEG], g1r[SEG];
        {
            float Aw = 1.f, Xw = 0.f;
            #pragma unroll
            for (int i = 0; i < SEG; i++) {
                const int t = w * SEG + i;
                float4 xa  = sm.xs[cb][t * 2];
                float4 xb4 = sm.xs[cb][t * 2 + 1];
                float xv[8] = {xa.x, xa.y, xa.z, xa.w, xb4.x, xb4.y, xb4.z, xb4.w};
                ull a01 = bias01, a23 = bias23;
                #pragma unroll
                for (int j = 0; j < F; j++) {
                    ull sp = splat2(xv[j]);
                    fma2(a01, sp, wp01[j]);
                    fma2(a23, sp, wp23[j]);
                }
                float2 eu1 = unpack2(a01);
                float2 gu2 = unpack2(a23);
                float d1, a1;
                splus_decay(eu1.y, A1k, d1, a1);
                float g1  = sigmoid_f(gu2.x);
                float xi1 = d1 * eu1.x;
                Xw = fmaf(a1, Xw, xi1);
                Aw *= a1;
                a1r[i] = a1; x1r[i] = xi1; g1r[i] = g1;
                sm.cEU[t * H + lane] = make_float2(eu1.x, gu2.y);
            }
            sm.segAX[0][w * H + lane] = make_float2(Aw, Xw);
        }
        __syncthreads();

        if (c + 1 < nchunk && tid < TCH * F / 4) {
            const float4* src = reinterpret_cast<const float4*>(x + (t0 + (c + 1) * TCH) * F);
            sm.xs[cb ^ 1][tid] = src[tid];
        }
        float st = 0.f;
        {
            float s = carry1;
            #pragma unroll
            for (int ww = 0; ww < NWARP; ww++) {
                float2 ax = sm.segAX[0][ww * H + lane];
                if (ww == w) st = s;
                s = fmaf(ax.x, s, ax.y);
            }
            carry1 = s;
        }
        {
            const float2* rd = sm.seg2[cb ^ 1];
            #pragma unroll
            for (int ww = 0; ww < NWARP; ww++) {
                float2 ax = rd[ww * H + lane];
                cX2 = fmaf(ax.x, cX2, ax.y);
                cA2 *= ax.x;
            }
        }
        float h1r[SEG];
        {
            float s1 = st;
            #pragma unroll
            for (int i = 0; i < SEG; i++) {
                const int t = w * SEG + i;
                s1 = fmaf(a1r[i], s1, x1r[i]);
                float v = s1 * g1r[i];
                h1r[i] = sm.cEU[t * H + lane].x + v;
                sm.cV[t * H + lane] = v;
            }
            if (q == 1 && c == nchunk - 1 && w == NWARP - 1)
                g_hlast[b * H + lane] = h1r[SEG - 1];
        }
        __syncwarp();
        {
            float A2 = 1.f, X2 = 0.f;
            #pragma unroll
            for (int i = 0; i < SEG; i++) {
                const int t = w * SEG + i;
                const longlong2* vr = reinterpret_cast<const longlong2*>(sm.cV + t * H);
                ull accA = 0ull, accB = 0ull;
                #pragma unroll
                for (int qd = 0; qd < 8; qd++) {
                    longlong2 vq = vr[qd];
                    fma2(accA, (ull)vq.x, wd2p[2 * qd]);
                    fma2(accB, (ull)vq.y, wd2p[2 * qd + 1]);
                }
                float2 fa = unpack2(accA), fb = unpack2(accB);
                float u2 = sm.cEU[t * H + lane].y + ((fa.x + fa.y) + (fb.x + fb.y));
                float d2, a2;
                splus_decay(u2, A2k, d2, a2);
                X2 = fmaf(a2, X2, d2 * h1r[i]);
                A2 *= a2;
            }
            sm.seg2[cb][w * H + lane] = make_float2(A2, X2);
        }
        __syncthreads();
    }

    // fold last chunk's block-2 partials, publish half transform
    {
        const float2* fin = sm.seg2[(nchunk - 1) & 1];
        #pragma unroll
        for (int ww = 0; ww < NWARP; ww++) {
            float2 ax = fin[ww * H + lane];
            cX2 = fmaf(ax.x, cX2, ax.y);
            cA2 *= ax.x;
        }
        if (w == 0) g_A2X2[q][b * H + lane] = make_float2(cA2, cX2);
    }
    __syncthreads();

    // ===== last-finisher epilogue (atomic handoff) =====
    if (tid == 0) {
        __threadfence();
        sm.sdone = atomicAdd(&g_done[b], 1);
    }
    __syncthreads();
    if (sm.sdone == 1 && w == 0) {
        __threadfence();
        const int i = b * H + lane;
        float2 T0 = g_A2X2[0][i];
        float2 T1 = g_A2X2[1][i];
        float s2 = fmaf(T1.x, T0.y, T1.y);
        float hl = g_hlast[i];
        float ug2 = bg[H + lane];
        #pragma unroll
        for (int j = 0; j < H; j++)
            ug2 = fmaf(__shfl_sync(FULL, hl, j), Wg[H * H + j * H + lane], ug2);
        float g2 = sigmoid_f(ug2);
        float h2 = hl + s2 * g2;
        float mu = warp_allsum(h2) * (1.f / H);
        float d  = h2 - mu;
        float var = warp_allsum(d * d) * (1.f / H);
        float hn = d * rsqrtf(var + 1e-5f) * gamma_[lane] + beta_[lane];
        float z1 = b1[lane];
        #pragma unroll
        for (int j = 0; j < H; j++)
            z1 = fmaf(__shfl_sync(FULL, hn, j), W1[j * H + lane], z1);
        float z = gelu_f(z1);
        float o = warp_allsum(z * W2[lane]);
        if (lane == 0) {
            out[b] = o + b2[0];
            g_done[b] = 0;   // reset for next graph replay (deterministic)
        }
    }
}

extern "C" void kernel_launch(void* const* d_in, const int* in_sizes, int n_in,
                              void* d_out, int out_size) {
    const float* x    = (const float*)d_in[0];
    const float* We   = (const float*)d_in[1];
    const float* be   = (const float*)d_in[2];
    const float* Wd   = (const float*)d_in[3];
    const float* bd   = (const float*)d_in[4];
    const float* Alog = (const float*)d_in[5];
    const float* Wg   = (const float*)d_in[6];
    const float* bg   = (const float*)d_in[7];
    const float* gam  = (const float*)d_in[8];
    const float* bet  = (const float*)d_in[9];
    const float* W1   = (const float*)d_in[10];
    const float* b1   = (const float*)d_in[11];
    const float* W2   = (const float*)d_in[12];
    const float* b2   = (const float*)d_in[13];
    float* out = (float*)d_out;

    int B = out_size;                  // 256
    int S = in_sizes[0] / (B * F);     // 4096

    setup_kernel<<<1, 256>>>(We, be, Wd, bd, Alog, Wg, bg);

    size_t smem = sizeof(SmemLayout);
    cudaFuncSetAttribute(forecast_kernel, cudaFuncAttributeMaxDynamicSharedMemorySize, (int)smem);
    forecast_kernel<<<dim3(B, 2), NTHR, smem>>>(x, Wd, Wg, bg, gam, bet,
                                                W1, b1, W2, b2, out, S);
}

// round 15
// speedup vs baseline: 1.1136x; 1.1136x over previous
#include <cuda_runtime.h>
#include <math.h>

#define H 32
#define F 8
#define FULL 0xffffffffu
#define BMAX 512
#define P 4                  // sequence split factor

// ---- shared geometry (K1 and K2) ----
#define TCH 32
#define NWARP 4
#define SEG (TCH / NWARP)    // 8
#define NTHR (NWARP * 32)    // 128

typedef unsigned long long ull;

__device__ float g_wX[4 * F * H];
__device__ float g_bias[4 * H];
__device__ float g_A[2 * H];

__device__ float2 g_T1[P - 1][BMAX * H];    // block-1 quarter transforms (q=0..2)
__device__ float2 g_A2X2[P][BMAX * H];      // block-2 quarter transforms
__device__ float  g_hlast[BMAX * H];
__device__ int    g_done[BMAX];

__device__ __forceinline__ float ex2f(float x) { float r; asm("ex2.approx.f32 %0,%1;" : "=f"(r) : "f"(x)); return r; }
__device__ __forceinline__ float lg2f(float x) { float r; asm("lg2.approx.f32 %0,%1;" : "=f"(r) : "f"(x)); return r; }
__device__ __forceinline__ float tanh_f(float x) { float r; asm("tanh.approx.f32 %0,%1;" : "=f"(r) : "f"(x)); return r; }

__device__ __forceinline__ ull pack2(float lo, float hi) {
    ull r; asm("mov.b64 %0, {%1, %2};" : "=l"(r) : "r"(__float_as_uint(lo)), "r"(__float_as_uint(hi)));
    return r;
}
__device__ __forceinline__ ull splat2(float x) {
    ull r; asm("mov.b64 %0, {%1, %1};" : "=l"(r) : "r"(__float_as_uint(x)));
    return r;
}
__device__ __forceinline__ float2 unpack2(ull v) {
    unsigned lo, hi; asm("mov.b64 {%0, %1}, %2;" : "=r"(lo), "=r"(hi) : "l"(v));
    return make_float2(__uint_as_float(lo), __uint_as_float(hi));
}
__device__ __forceinline__ void fma2(ull& d, ull a, ull b) {
    asm("fma.rn.f32x2 %0, %1, %2, %0;" : "+l"(d) : "l"(a), "l"(b));
}

__device__ __forceinline__ void splus_decay(float u, float A, float& d, float& a) {
    const float L2E = 1.4426950408889634f;
    const float LN2 = 0.6931471805599453f;
    float p = ex2f(-fabsf(u) * L2E);
    float q = lg2f(1.f + p);
    float r = fmaf(fmaxf(u, 0.f), L2E, q);
    d = r * LN2;
    a = ex2f(-A * r);
}

__device__ __forceinline__ float sigmoid_f(float u) {
    return fmaf(tanh_f(0.5f * u), 0.5f, 0.5f);
}

__device__ __forceinline__ float gelu_f(float u) {
    float inner = 0.7978845608028654f * fmaf(0.044715f * u, u * u, u);
    float ex = ex2f(2.f * inner * 1.4426950408889634f);
    float th = 1.f - __fdividef(2.f, ex + 1.f);
    return 0.5f * u * (1.f + th);
}

__device__ __forceinline__ float warp_allsum(float v) {
    #pragma unroll
    for (int off = 16; off; off >>= 1) v += __shfl_xor_sync(FULL, v, off);
    return v;
}

__global__ void setup_kernel(const float* __restrict__ We, const float* __restrict__ be,
                             const float* __restrict__ Wd, const float* __restrict__ bd,
                             const float* __restrict__ Alog, const float* __restrict__ Wg,
                             const float* __restrict__ bg) {
    int tid = threadIdx.x;
    for (int idx = tid; idx < F * H; idx += blockDim.x) g_wX[idx] = We[idx];
    for (int idx = tid; idx < 3 * F * H; idx += blockDim.x) {
        int m = idx / (F * H);
        int r = idx % (F * H);
        int f = r / H, k = r % H;
        const float* M = (m == 0) ? Wd : (m == 1) ? Wg : (Wd + H * H);
        float s = 0.f;
        for (int h = 0; h < H; h++) s += We[f * H + h] * M[h * H + k];
        g_wX[(m + 1) * F * H + r] = s;
    }
    for (int idx = tid; idx < 4 * H; idx += blockDim.x) {
        int m = idx / H, k = idx % H;
        float v;
        if (m == 0) v = be[k];
        else {
            const float* M; const float* bb;
            if (m == 1)      { M = Wd;         bb = bd;     }
            else if (m == 2) { M = Wg;         bb = bg;     }
            else             { M = Wd + H * H; bb = bd + H; }
            float s = 0.f;
            for (int h = 0; h < H; h++) s += be[h] * M[h * H + k];
            v = s + bb[k];
        }
        g_bias[idx] = v;
    }
    for (int idx = tid; idx < 2 * H; idx += blockDim.x) g_A[idx] = expf(Alog[idx]);
    for (int idx = tid; idx < BMAX; idx += blockDim.x) g_done[idx] = 0;
}

// =========== K1: block-1 quarter transform (q = 0..2), lite, occ-4 =========
struct Smem1 {
    float4 xs[2][TCH * F / 4];
    float2 segAX[2][NWARP * H];
    float2 swp01[F * H];
    float  sb01[2 * H];
    float  sA1[H];
};

__global__ void __launch_bounds__(NTHR, 4)
block1_seg_kernel(const float* __restrict__ x, int S) {
    extern __shared__ float smraw[];
    Smem1& sm = *reinterpret_cast<Smem1*>(smraw);
    const int tid  = threadIdx.x;
    const int lane = tid & 31;
    const int w    = tid >> 5;
    const int b    = blockIdx.x;
    const int q    = blockIdx.y;           // 0..P-2
    const int qlen = S / P;
    const long t0  = (long)b * S + (long)q * qlen;
    const int nchunk = qlen / TCH;

    for (int i = tid; i < F * H; i += NTHR) {
        int j = i / H, k = i % H;
        sm.swp01[i] = make_float2(g_wX[0 * F * H + j * H + k], g_wX[1 * F * H + j * H + k]);
    }
    for (int i = tid; i < 2 * H; i += NTHR) sm.sb01[i] = g_bias[i];
    for (int i = tid; i < H; i += NTHR) sm.sA1[i] = g_A[i];
    if (tid < TCH * F / 4) {
        const float4* src = reinterpret_cast<const float4*>(x + t0 * F);
        sm.xs[0][tid] = src[tid];
    }
    __syncthreads();

    ull wp01[F];
    #pragma unroll
    for (int j = 0; j < F; j++) {
        float2 p0 = sm.swp01[j * H + lane];
        wp01[j] = pack2(p0.x, p0.y);
    }
    const ull bias01 = pack2(sm.sb01[lane], sm.sb01[H + lane]);
    const float A1k = sm.sA1[lane];

    float Ar = 1.f, Xr = 0.f;   // running quarter transform (replicated)
    for (int c = 0; c < nchunk; c++) {
        const int cb = c & 1;
        {
            float Aw = 1.f, Xw = 0.f;
            #pragma unroll
            for (int i = 0; i < SEG; i++) {
                const int t = w * SEG + i;
                float4 xa  = sm.xs[cb][t * 2];
                float4 xb4 = sm.xs[cb][t * 2 + 1];
                float xv[8] = {xa.x, xa.y, xa.z, xa.w, xb4.x, xb4.y, xb4.z, xb4.w};
                ull a01 = bias01;
                #pragma unroll
                for (int j = 0; j < F; j++) fma2(a01, splat2(xv[j]), wp01[j]);
                float2 eu1 = unpack2(a01);
                float d1, a1;
                splus_decay(eu1.y, A1k, d1, a1);
                Xw = fmaf(a1, Xw, d1 * eu1.x);
                Aw *= a1;
            }
            sm.segAX[cb][w * H + lane] = make_float2(Aw, Xw);
        }
        if (c + 1 < nchunk && tid < TCH * F / 4) {
            const float4* src = reinterpret_cast<const float4*>(x + (t0 + (c + 1) * TCH) * F);
            sm.xs[cb ^ 1][tid] = src[tid];
        }
        __syncthreads();
        #pragma unroll
        for (int ww = 0; ww < NWARP; ww++) {
            float2 ax = sm.segAX[cb][ww * H + lane];
            Xr = fmaf(ax.x, Xr, ax.y);
            Ar *= ax.x;
        }
    }
    if (w == 0) g_T1[q][b * H + lane] = make_float2(Ar, Xr);
}

// =========== K2: quarter pipeline + fused last-finisher epilogue ==========
struct Smem2 {
    float4 xs[2][TCH * F / 4];
    float2 cEU[TCH * H];
    float  cV[TCH * H];
    float2 segAX[NWARP * H];
    float2 seg2[2][NWARP * H];
    float2 swp01[F * H];
    float2 swp23[F * H];
    float2 swd2p[(H / 2) * H];
    float  sbias[4 * H];
    float  sA[2 * H];
    int    sdone;
};

__global__ void __launch_bounds__(NTHR, 4)
forecast_quarter_kernel(const float* __restrict__ x, const float* __restrict__ Wd,
                        const float* __restrict__ Wg, const float* __restrict__ bg,
                        const float* __restrict__ gamma_, const float* __restrict__ beta_,
                        const float* __restrict__ W1, const float* __restrict__ b1,
                        const float* __restrict__ W2, const float* __restrict__ b2,
                        float* __restrict__ out, int S) {
    extern __shared__ float smraw[];
    Smem2& sm = *reinterpret_cast<Smem2*>(smraw);
    const int tid  = threadIdx.x;
    const int lane = tid & 31;
    const int w    = tid >> 5;
    const int b    = blockIdx.x;
    const int q    = blockIdx.y;            // 0..P-1
    const int qlen = S / P;
    const long t0  = (long)b * S + (long)q * qlen;
    const int nchunk = qlen / TCH;

    for (int i = tid; i < F * H; i += NTHR) {
        int j = i / H, k = i % H;
        sm.swp01[i] = make_float2(g_wX[0 * F * H + j * H + k], g_wX[1 * F * H + j * H + k]);
        sm.swp23[i] = make_float2(g_wX[2 * F * H + j * H + k], g_wX[3 * F * H + j * H + k]);
    }
    for (int i = tid; i < (H / 2) * H; i += NTHR) {
        int p = i / H, k = i % H;
        sm.swd2p[i] = make_float2(Wd[H * H + (2 * p) * H + k], Wd[H * H + (2 * p + 1) * H + k]);
    }
    for (int i = tid; i < 4 * H; i += NTHR) sm.sbias[i] = g_bias[i];
    for (int i = tid; i < 2 * H; i += NTHR) sm.sA[i] = g_A[i];
    if (tid < TCH * F / 4) {
        const float4* src = reinterpret_cast<const float4*>(x + t0 * F);
        sm.xs[0][tid] = src[tid];
    }
    if (tid < NWARP * H) sm.seg2[1][tid] = make_float2(1.f, 0.f);
    __syncthreads();

    ull wp01[F], wp23[F];
    #pragma unroll
    for (int j = 0; j < F; j++) {
        float2 p0 = sm.swp01[j * H + lane];
        float2 p2 = sm.swp23[j * H + lane];
        wp01[j] = pack2(p0.x, p0.y);
        wp23[j] = pack2(p2.x, p2.y);
    }
    ull wd2p[H / 2];
    #pragma unroll
    for (int p = 0; p < H / 2; p++) {
        float2 wv = sm.swd2p[p * H + lane];
        wd2p[p] = pack2(wv.x, wv.y);
    }
    const ull bias01 = pack2(sm.sbias[lane],         sm.sbias[H + lane]);
    const ull bias23 = pack2(sm.sbias[2 * H + lane], sm.sbias[3 * H + lane]);
    const float A1k = sm.sA[lane];
    const float A2k = sm.sA[H + lane];

    // compose block-1 prefix state for this quarter from K1 transforms
    float carry1 = 0.f;
    for (int qq = 0; qq < q; qq++) {
        float2 T = g_T1[qq][b * H + lane];
        carry1 = fmaf(T.x, carry1, T.y);
    }
    float cA2 = 1.f, cX2 = 0.f;

    for (int c = 0; c < nchunk; c++) {
        const int cb = c & 1;
        float a1r[SEG], x1r[SEG], g1r[SEG];
        {
            float Aw = 1.f, Xw = 0.f;
            #pragma unroll
            for (int i = 0; i < SEG; i++) {
                const int t = w * SEG + i;
                float4 xa  = sm.xs[cb][t * 2];
                float4 xb4 = sm.xs[cb][t * 2 + 1];
                float xv[8] = {xa.x, xa.y, xa.z, xa.w, xb4.x, xb4.y, xb4.z, xb4.w};
                ull a01 = bias01, a23 = bias23;
                #pragma unroll
                for (int j = 0; j < F; j++) {
                    ull sp = splat2(xv[j]);
                    fma2(a01, sp, wp01[j]);
                    fma2(a23, sp, wp23[j]);
                }
                float2 eu1 = unpack2(a01);
                float2 gu2 = unpack2(a23);
                float d1, a1;
                splus_decay(eu1.y, A1k, d1, a1);
                float g1  = sigmoid_f(gu2.x);
                float xi1 = d1 * eu1.x;
                Xw = fmaf(a1, Xw, xi1);
                Aw *= a1;
                a1r[i] = a1; x1r[i] = xi1; g1r[i] = g1;
                sm.cEU[t * H + lane] = make_float2(eu1.x, gu2.y);
            }
            sm.segAX[w * H + lane] = make_float2(Aw, Xw);
        }
        __syncthreads();

        if (c + 1 < nchunk && tid < TCH * F / 4) {
            const float4* src = reinterpret_cast<const float4*>(x + (t0 + (c + 1) * TCH) * F);
            sm.xs[cb ^ 1][tid] = src[tid];
        }
        float st = 0.f;
        {
            float s = carry1;
            #pragma unroll
            for (int ww = 0; ww < NWARP; ww++) {
                float2 ax = sm.segAX[ww * H + lane];
                if (ww == w) st = s;
                s = fmaf(ax.x, s, ax.y);
            }
            carry1 = s;
        }
        {
            const float2* rd = sm.seg2[cb ^ 1];
            #pragma unroll
            for (int ww = 0; ww < NWARP; ww++) {
                float2 ax = rd[ww * H + lane];
                cX2 = fmaf(ax.x, cX2, ax.y);
                cA2 *= ax.x;
            }
        }
        float h1r[SEG];
        {
            float s1 = st;
            #pragma unroll
            for (int i = 0; i < SEG; i++) {
                const int t = w * SEG + i;
                s1 = fmaf(a1r[i], s1, x1r[i]);
                float v = s1 * g1r[i];
                h1r[i] = sm.cEU[t * H + lane].x + v;
                sm.cV[t * H + lane] = v;
            }
            if (q == P - 1 && c == nchunk - 1 && w == NWARP - 1)
                g_hlast[b * H + lane] = h1r[SEG - 1];
        }
        __syncwarp();
        {
            float A2 = 1.f, X2 = 0.f;
            #pragma unroll
            for (int i = 0; i < SEG; i++) {
                const int t = w * SEG + i;
                const longlong2* vr = reinterpret_cast<const longlong2*>(sm.cV + t * H);
                ull accA = 0ull, accB = 0ull;
                #pragma unroll
                for (int qd = 0; qd < 8; qd++) {
                    longlong2 vq = vr[qd];
                    fma2(accA, (ull)vq.x, wd2p[2 * qd]);
                    fma2(accB, (ull)vq.y, wd2p[2 * qd + 1]);
                }
                float2 fa = unpack2(accA), fb = unpack2(accB);
                float u2 = sm.cEU[t * H + lane].y + ((fa.x + fa.y) + (fb.x + fb.y));
                float d2, a2;
                splus_decay(u2, A2k, d2, a2);
                X2 = fmaf(a2, X2, d2 * h1r[i]);
                A2 *= a2;
            }
            sm.seg2[cb][w * H + lane] = make_float2(A2, X2);
        }
        __syncthreads();
    }

    // fold last chunk's block-2 partials, publish quarter transform
    {
        const float2* fin = sm.seg2[(nchunk - 1) & 1];
        #pragma unroll
        for (int ww = 0; ww < NWARP; ww++) {
            float2 ax = fin[ww * H + lane];
            cX2 = fmaf(ax.x, cX2, ax.y);
            cA2 *= ax.x;
        }
        if (w == 0) g_A2X2[q][b * H + lane] = make_float2(cA2, cX2);
    }
    __syncthreads();

    // ===== last-finisher epilogue (atomic handoff, validated in R14) =====
    if (tid == 0) {
        __threadfence();
        sm.sdone = atomicAdd(&g_done[b], 1);
    }
    __syncthreads();
    if (sm.sdone == P - 1 && w == 0) {
        __threadfence();
        const int i = b * H + lane;
        float s2 = 0.f;
        #pragma unroll
        for (int qq = 0; qq < P; qq++) {
            float2 T = g_A2X2[qq][i];
            s2 = fmaf(T.x, s2, T.y);
        }
        float hl = g_hlast[i];
        float ug2 = bg[H + lane];
        #pragma unroll
        for (int j = 0; j < H; j++)
            ug2 = fmaf(__shfl_sync(FULL, hl, j), Wg[H * H + j * H + lane], ug2);
        float g2 = sigmoid_f(ug2);
        float h2 = hl + s2 * g2;
        float mu = warp_allsum(h2) * (1.f / H);
        float d  = h2 - mu;
        float var = warp_allsum(d * d) * (1.f / H);
        float hn = d * rsqrtf(var + 1e-5f) * gamma_[lane] + beta_[lane];
        float z1 = b1[lane];
        #pragma unroll
        for (int j = 0; j < H; j++)
            z1 = fmaf(__shfl_sync(FULL, hn, j), W1[j * H + lane], z1);
        float z = gelu_f(z1);
        float o = warp_allsum(z * W2[lane]);
        if (lane == 0) {
            out[b] = o + b2[0];
            g_done[b] = 0;   // reset for next graph replay (deterministic)
        }
    }
}

extern "C" void kernel_launch(void* const* d_in, const int* in_sizes, int n_in,
                              void* d_out, int out_size) {
    const float* x    = (const float*)d_in[0];
    const float* We   = (const float*)d_in[1];
    const float* be   = (const float*)d_in[2];
    const float* Wd   = (const float*)d_in[3];
    const float* bd   = (const float*)d_in[4];
    const float* Alog = (const float*)d_in[5];
    const float* Wg   = (const float*)d_in[6];
    const float* bg   = (const float*)d_in[7];
    const float* gam  = (const float*)d_in[8];
    const float* bet  = (const float*)d_in[9];
    const float* W1   = (const float*)d_in[10];
    const float* b1   = (const float*)d_in[11];
    const float* W2   = (const float*)d_in[12];
    const float* b2   = (const float*)d_in[13];
    float* out = (float*)d_out;

    int B = out_size;                  // 256
    int S = in_sizes[0] / (B * F);     // 4096

    setup_kernel<<<1, 256>>>(We, be, Wd, bd, Alog, Wg, bg);

    size_t smem1 = sizeof(Smem1);
    cudaFuncSetAttribute(block1_seg_kernel, cudaFuncAttributeMaxDynamicSharedMemorySize, (int)smem1);
    block1_seg_kernel<<<dim3(B, P - 1), NTHR, smem1>>>(x, S);

    size_t smem2 = sizeof(Smem2);
    cudaFuncSetAttribute(forecast_quarter_kernel, cudaFuncAttributeMaxDynamicSharedMemorySize, (int)smem2);
    forecast_quarter_kernel<<<dim3(B, P), NTHR, smem2>>>(x, Wd, Wg, bg, gam, bet,
                                                          W1, b1, W2, b2, out, S);
}

// round 16
// speedup vs baseline: 1.1528x; 1.0352x over previous
#include <cuda_runtime.h>
#include <math.h>

#define H 32
#define F 8
#define FULL 0xffffffffu
#define BMAX 512
#define P 4                  // main split factor (quarters)
#define E 8                  // lite split factor (eighths)
#define NE (E - 2)           // # eighth transforms needed (0..5)

// ---- shared geometry (K1 and K2) ----
#define TCH 32
#define NWARP 4
#define SEG (TCH / NWARP)    // 8
#define NTHR (NWARP * 32)    // 128

typedef unsigned long long ull;

__device__ float g_wX[4 * F * H];
__device__ float g_bias[4 * H];
__device__ float g_A[2 * H];

__device__ float2 g_T1[NE][BMAX * H];       // block-1 eighth transforms (e=0..5)
__device__ float2 g_A2X2[P][BMAX * H];      // block-2 quarter transforms
__device__ float  g_hlast[BMAX * H];
__device__ int    g_done[BMAX];

__device__ __forceinline__ float ex2f(float x) { float r; asm("ex2.approx.f32 %0,%1;" : "=f"(r) : "f"(x)); return r; }
__device__ __forceinline__ float lg2f(float x) { float r; asm("lg2.approx.f32 %0,%1;" : "=f"(r) : "f"(x)); return r; }
__device__ __forceinline__ float tanh_f(float x) { float r; asm("tanh.approx.f32 %0,%1;" : "=f"(r) : "f"(x)); return r; }

__device__ __forceinline__ ull pack2(float lo, float hi) {
    ull r; asm("mov.b64 %0, {%1, %2};" : "=l"(r) : "r"(__float_as_uint(lo)), "r"(__float_as_uint(hi)));
    return r;
}
__device__ __forceinline__ ull splat2(float x) {
    ull r; asm("mov.b64 %0, {%1, %1};" : "=l"(r) : "r"(__float_as_uint(x)));
    return r;
}
__device__ __forceinline__ float2 unpack2(ull v) {
    unsigned lo, hi; asm("mov.b64 {%0, %1}, %2;" : "=r"(lo), "=r"(hi) : "l"(v));
    return make_float2(__uint_as_float(lo), __uint_as_float(hi));
}
__device__ __forceinline__ void fma2(ull& d, ull a, ull b) {
    asm("fma.rn.f32x2 %0, %1, %2, %0;" : "+l"(d) : "l"(a), "l"(b));
}

__device__ __forceinline__ void splus_decay(float u, float A, float& d, float& a) {
    const float L2E = 1.4426950408889634f;
    const float LN2 = 0.6931471805599453f;
    float p = ex2f(-fabsf(u) * L2E);
    float q = lg2f(1.f + p);
    float r = fmaf(fmaxf(u, 0.f), L2E, q);
    d = r * LN2;
    a = ex2f(-A * r);
}

__device__ __forceinline__ float sigmoid_f(float u) {
    return fmaf(tanh_f(0.5f * u), 0.5f, 0.5f);
}

__device__ __forceinline__ float gelu_f(float u) {
    float inner = 0.7978845608028654f * fmaf(0.044715f * u, u * u, u);
    float ex = ex2f(2.f * inner * 1.4426950408889634f);
    float th = 1.f - __fdividef(2.f, ex + 1.f);
    return 0.5f * u * (1.f + th);
}

__device__ __forceinline__ float warp_allsum(float v) {
    #pragma unroll
    for (int off = 16; off; off >>= 1) v += __shfl_xor_sync(FULL, v, off);
    return v;
}

// Parallelized setup: grid-stride over all fold work (grid = 32 blocks).
__global__ void setup_kernel(const float* __restrict__ We, const float* __restrict__ be,
                             const float* __restrict__ Wd, const float* __restrict__ bd,
                             const float* __restrict__ Alog, const float* __restrict__ Wg,
                             const float* __restrict__ bg) {
    int tid = threadIdx.x + blockIdx.x * blockDim.x;
    int nth = blockDim.x * gridDim.x;
    for (int idx = tid; idx < F * H; idx += nth) g_wX[idx] = We[idx];
    for (int idx = tid; idx < 3 * F * H; idx += nth) {
        int m = idx / (F * H);
        int r = idx % (F * H);
        int f = r / H, k = r % H;
        const float* M = (m == 0) ? Wd : (m == 1) ? Wg : (Wd + H * H);
        float s = 0.f;
        for (int h = 0; h < H; h++) s += We[f * H + h] * M[h * H + k];
        g_wX[(m + 1) * F * H + r] = s;
    }
    for (int idx = tid; idx < 4 * H; idx += nth) {
        int m = idx / H, k = idx % H;
        float v;
        if (m == 0) v = be[k];
        else {
            const float* M; const float* bb;
            if (m == 1)      { M = Wd;         bb = bd;     }
            else if (m == 2) { M = Wg;         bb = bg;     }
            else             { M = Wd + H * H; bb = bd + H; }
            float s = 0.f;
            for (int h = 0; h < H; h++) s += be[h] * M[h * H + k];
            v = s + bb[k];
        }
        g_bias[idx] = v;
    }
    for (int idx = tid; idx < 2 * H; idx += nth) g_A[idx] = expf(Alog[idx]);
    for (int idx = tid; idx < BMAX; idx += nth) g_done[idx] = 0;
}

// =========== K1: block-1 EIGHTH transforms (e = 0..5), lite, occ-4 =========
struct Smem1 {
    float4 xs[2][TCH * F / 4];
    float2 segAX[2][NWARP * H];
    float2 swp01[F * H];
    float  sb01[2 * H];
    float  sA1[H];
};

__global__ void __launch_bounds__(NTHR, 4)
block1_seg_kernel(const float* __restrict__ x, int S) {
    extern __shared__ float smraw[];
    Smem1& sm = *reinterpret_cast<Smem1*>(smraw);
    const int tid  = threadIdx.x;
    const int lane = tid & 31;
    const int w    = tid >> 5;
    const int b    = blockIdx.x;
    const int e    = blockIdx.y;           // 0..NE-1
    const int elen = S / E;
    const long t0  = (long)b * S + (long)e * elen;
    const int nchunk = elen / TCH;

    for (int i = tid; i < F * H; i += NTHR) {
        int j = i / H, k = i % H;
        sm.swp01[i] = make_float2(g_wX[0 * F * H + j * H + k], g_wX[1 * F * H + j * H + k]);
    }
    for (int i = tid; i < 2 * H; i += NTHR) sm.sb01[i] = g_bias[i];
    for (int i = tid; i < H; i += NTHR) sm.sA1[i] = g_A[i];
    if (tid < TCH * F / 4) {
        const float4* src = reinterpret_cast<const float4*>(x + t0 * F);
        sm.xs[0][tid] = src[tid];
    }
    __syncthreads();

    ull wp01[F];
    #pragma unroll
    for (int j = 0; j < F; j++) {
        float2 p0 = sm.swp01[j * H + lane];
        wp01[j] = pack2(p0.x, p0.y);
    }
    const ull bias01 = pack2(sm.sb01[lane], sm.sb01[H + lane]);
    const float A1k = sm.sA1[lane];

    float Ar = 1.f, Xr = 0.f;   // running eighth transform (replicated)
    for (int c = 0; c < nchunk; c++) {
        const int cb = c & 1;
        {
            float Aw = 1.f, Xw = 0.f;
            #pragma unroll
            for (int i = 0; i < SEG; i++) {
                const int t = w * SEG + i;
                float4 xa  = sm.xs[cb][t * 2];
                float4 xb4 = sm.xs[cb][t * 2 + 1];
                float xv[8] = {xa.x, xa.y, xa.z, xa.w, xb4.x, xb4.y, xb4.z, xb4.w};
                ull a01 = bias01;
                #pragma unroll
                for (int j = 0; j < F; j++) fma2(a01, splat2(xv[j]), wp01[j]);
                float2 eu1 = unpack2(a01);
                float d1, a1;
                splus_decay(eu1.y, A1k, d1, a1);
                Xw = fmaf(a1, Xw, d1 * eu1.x);
                Aw *= a1;
            }
            sm.segAX[cb][w * H + lane] = make_float2(Aw, Xw);
        }
        if (c + 1 < nchunk && tid < TCH * F / 4) {
            const float4* src = reinterpret_cast<const float4*>(x + (t0 + (c + 1) * TCH) * F);
            sm.xs[cb ^ 1][tid] = src[tid];
        }
        __syncthreads();
        #pragma unroll
        for (int ww = 0; ww < NWARP; ww++) {
            float2 ax = sm.segAX[cb][ww * H + lane];
            Xr = fmaf(ax.x, Xr, ax.y);
            Ar *= ax.x;
        }
    }
    if (w == 0) g_T1[e][b * H + lane] = make_float2(Ar, Xr);
}

// =========== K2: quarter pipeline + fused last-finisher epilogue ==========
struct Smem2 {
    float4 xs[2][TCH * F / 4];
    float2 cEU[TCH * H];
    float  cV[TCH * H];
    float2 segAX[NWARP * H];
    float2 seg2[2][NWARP * H];
    float2 swp01[F * H];
    float2 swp23[F * H];
    float2 swd2p[(H / 2) * H];
    float  sbias[4 * H];
    float  sA[2 * H];
    int    sdone;
};

__global__ void __launch_bounds__(NTHR, 4)
forecast_quarter_kernel(const float* __restrict__ x, const float* __restrict__ Wd,
                        const float* __restrict__ Wg, const float* __restrict__ bg,
                        const float* __restrict__ gamma_, const float* __restrict__ beta_,
                        const float* __restrict__ W1, const float* __restrict__ b1,
                        const float* __restrict__ W2, const float* __restrict__ b2,
                        float* __restrict__ out, int S) {
    extern __shared__ float smraw[];
    Smem2& sm = *reinterpret_cast<Smem2*>(smraw);
    const int tid  = threadIdx.x;
    const int lane = tid & 31;
    const int w    = tid >> 5;
    const int b    = blockIdx.x;
    const int q    = blockIdx.y;            // 0..P-1
    const int qlen = S / P;
    const long t0  = (long)b * S + (long)q * qlen;
    const int nchunk = qlen / TCH;

    for (int i = tid; i < F * H; i += NTHR) {
        int j = i / H, k = i % H;
        sm.swp01[i] = make_float2(g_wX[0 * F * H + j * H + k], g_wX[1 * F * H + j * H + k]);
        sm.swp23[i] = make_float2(g_wX[2 * F * H + j * H + k], g_wX[3 * F * H + j * H + k]);
    }
    for (int i = tid; i < (H / 2) * H; i += NTHR) {
        int p = i / H, k = i % H;
        sm.swd2p[i] = make_float2(Wd[H * H + (2 * p) * H + k], Wd[H * H + (2 * p + 1) * H + k]);
    }
    for (int i = tid; i < 4 * H; i += NTHR) sm.sbias[i] = g_bias[i];
    for (int i = tid; i < 2 * H; i += NTHR) sm.sA[i] = g_A[i];
    if (tid < TCH * F / 4) {
        const float4* src = reinterpret_cast<const float4*>(x + t0 * F);
        sm.xs[0][tid] = src[tid];
    }
    if (tid < NWARP * H) sm.seg2[1][tid] = make_float2(1.f, 0.f);
    __syncthreads();

    ull wp01[F], wp23[F];
    #pragma unroll
    for (int j = 0; j < F; j++) {
        float2 p0 = sm.swp01[j * H + lane];
        float2 p2 = sm.swp23[j * H + lane];
        wp01[j] = pack2(p0.x, p0.y);
        wp23[j] = pack2(p2.x, p2.y);
    }
    ull wd2p[H / 2];
    #pragma unroll
    for (int p = 0; p < H / 2; p++) {
        float2 wv = sm.swd2p[p * H + lane];
        wd2p[p] = pack2(wv.x, wv.y);
    }
    const ull bias01 = pack2(sm.sbias[lane],         sm.sbias[H + lane]);
    const ull bias23 = pack2(sm.sbias[2 * H + lane], sm.sbias[3 * H + lane]);
    const float A1k = sm.sA[lane];
    const float A2k = sm.sA[H + lane];

    // compose block-1 prefix state for this quarter from eighth transforms 0..2q-1
    float carry1 = 0.f;
    for (int ee = 0; ee < 2 * q; ee++) {
        float2 T = g_T1[ee][b * H + lane];
        carry1 = fmaf(T.x, carry1, T.y);
    }
    float cA2 = 1.f, cX2 = 0.f;

    for (int c = 0; c < nchunk; c++) {
        const int cb = c & 1;
        float a1r[SEG], x1r[SEG], g1r[SEG];
        {
            float Aw = 1.f, Xw = 0.f;
            #pragma unroll
            for (int i = 0; i < SEG; i++) {
                const int t = w * SEG + i;
                float4 xa  = sm.xs[cb][t * 2];
                float4 xb4 = sm.xs[cb][t * 2 + 1];
                float xv[8] = {xa.x, xa.y, xa.z, xa.w, xb4.x, xb4.y, xb4.z, xb4.w};
                ull a01 = bias01, a23 = bias23;
                #pragma unroll
                for (int j = 0; j < F; j++) {
                    ull sp = splat2(xv[j]);
                    fma2(a01, sp, wp01[j]);
                    fma2(a23, sp, wp23[j]);
                }
                float2 eu1 = unpack2(a01);
                float2 gu2 = unpack2(a23);
                float d1, a1;
                splus_decay(eu1.y, A1k, d1, a1);
                float g1  = sigmoid_f(gu2.x);
                float xi1 = d1 * eu1.x;
                Xw = fmaf(a1, Xw, xi1);
                Aw *= a1;
                a1r[i] = a1; x1r[i] = xi1; g1r[i] = g1;
                sm.cEU[t * H + lane] = make_float2(eu1.x, gu2.y);
            }
            sm.segAX[w * H + lane] = make_float2(Aw, Xw);
        }
        __syncthreads();

        if (c + 1 < nchunk && tid < TCH * F / 4) {
            const float4* src = reinterpret_cast<const float4*>(x + (t0 + (c + 1) * TCH) * F);
            sm.xs[cb ^ 1][tid] = src[tid];
        }
        float st = 0.f;
        {
            float s = carry1;
            #pragma unroll
            for (int ww = 0; ww < NWARP; ww++) {
                float2 ax = sm.segAX[ww * H + lane];
                if (ww == w) st = s;
                s = fmaf(ax.x, s, ax.y);
            }
            carry1 = s;
        }
        {
            const float2* rd = sm.seg2[cb ^ 1];
            #pragma unroll
            for (int ww = 0; ww < NWARP; ww++) {
                float2 ax = rd[ww * H + lane];
                cX2 = fmaf(ax.x, cX2, ax.y);
                cA2 *= ax.x;
            }
        }
        float h1r[SEG];
        {
            float s1 = st;
            #pragma unroll
            for (int i = 0; i < SEG; i++) {
                const int t = w * SEG + i;
                s1 = fmaf(a1r[i], s1, x1r[i]);
                float v = s1 * g1r[i];
                h1r[i] = sm.cEU[t * H + lane].x + v;
                sm.cV[t * H + lane] = v;
            }
            if (q == P - 1 && c == nchunk - 1 && w == NWARP - 1)
                g_hlast[b * H + lane] = h1r[SEG - 1];
        }
        __syncwarp();
        {
            float A2 = 1.f, X2 = 0.f;
            #pragma unroll
            for (int i = 0; i < SEG; i++) {
                const int t = w * SEG + i;
                const longlong2* vr = reinterpret_cast<const longlong2*>(sm.cV + t * H);
                ull accA = 0ull, accB = 0ull;
                #pragma unroll
                for (int qd = 0; qd < 8; qd++) {
                    longlong2 vq = vr[qd];
                    fma2(accA, (ull)vq.x, wd2p[2 * qd]);
                    fma2(accB, (ull)vq.y, wd2p[2 * qd + 1]);
                }
                float2 fa = unpack2(accA), fb = unpack2(accB);
                float u2 = sm.cEU[t * H + lane].y + ((fa.x + fa.y) + (fb.x + fb.y));
                float d2, a2;
                splus_decay(u2, A2k, d2, a2);
                X2 = fmaf(a2, X2, d2 * h1r[i]);
                A2 *= a2;
            }
            sm.seg2[cb][w * H + lane] = make_float2(A2, X2);
        }
        __syncthreads();
    }

    // fold last chunk's block-2 partials, publish quarter transform
    {
        const float2* fin = sm.seg2[(nchunk - 1) & 1];
        #pragma unroll
        for (int ww = 0; ww < NWARP; ww++) {
            float2 ax = fin[ww * H + lane];
            cX2 = fmaf(ax.x, cX2, ax.y);
            cA2 *= ax.x;
        }
        if (w == 0) g_A2X2[q][b * H + lane] = make_float2(cA2, cX2);
    }
    __syncthreads();

    // ===== last-finisher epilogue (atomic handoff) =====
    if (tid == 0) {
        __threadfence();
        sm.sdone = atomicAdd(&g_done[b], 1);
    }
    __syncthreads();
    if (sm.sdone == P - 1 && w == 0) {
        __threadfence();
        const int i = b * H + lane;
        float s2 = 0.f;
        #pragma unroll
        for (int qq = 0; qq < P; qq++) {
            float2 T = g_A2X2[qq][i];
            s2 = fmaf(T.x, s2, T.y);
        }
        float hl = g_hlast[i];
        float ug2 = bg[H + lane];
        #pragma unroll
        for (int j = 0; j < H; j++)
            ug2 = fmaf(__shfl_sync(FULL, hl, j), Wg[H * H + j * H + lane], ug2);
        float g2 = sigmoid_f(ug2);
        float h2 = hl + s2 * g2;
        float mu = warp_allsum(h2) * (1.f / H);
        float d  = h2 - mu;
        float var = warp_allsum(d * d) * (1.f / H);
        float hn = d * rsqrtf(var + 1e-5f) * gamma_[lane] + beta_[lane];
        float z1 = b1[lane];
        #pragma unroll
        for (int j = 0; j < H; j++)
            z1 = fmaf(__shfl_sync(FULL, hn, j), W1[j * H + lane], z1);
        float z = gelu_f(z1);
        float o = warp_allsum(z * W2[lane]);
        if (lane == 0) {
            out[b] = o + b2[0];
            g_done[b] = 0;   // reset for next graph replay (deterministic)
        }
    }
}

extern "C" void kernel_launch(void* const* d_in, const int* in_sizes, int n_in,
                              void* d_out, int out_size) {
    const float* x    = (const float*)d_in[0];
    const float* We   = (const float*)d_in[1];
    const float* be   = (const float*)d_in[2];
    const float* Wd   = (const float*)d_in[3];
    const float* bd   = (const float*)d_in[4];
    const float* Alog = (const float*)d_in[5];
    const float* Wg   = (const float*)d_in[6];
    const float* bg   = (const float*)d_in[7];
    const float* gam  = (const float*)d_in[8];
    const float* bet  = (const float*)d_in[9];
    const float* W1   = (const float*)d_in[10];
    const float* b1   = (const float*)d_in[11];
    const float* W2   = (const float*)d_in[12];
    const float* b2   = (const float*)d_in[13];
    float* out = (float*)d_out;

    int B = out_size;                  // 256
    int S = in_sizes[0] / (B * F);     // 4096

    setup_kernel<<<32, 256>>>(We, be, Wd, bd, Alog, Wg, bg);

    size_t smem1 = sizeof(Smem1);
    cudaFuncSetAttribute(block1_seg_kernel, cudaFuncAttributeMaxDynamicSharedMemorySize, (int)smem1);
    block1_seg_kernel<<<dim3(B, NE), NTHR, smem1>>>(x, S);

    size_t smem2 = sizeof(Smem2);
    cudaFuncSetAttribute(forecast_quarter_kernel, cudaFuncAttributeMaxDynamicSharedMemorySize, (int)smem2);
    forecast_quarter_kernel<<<dim3(B, P), NTHR, smem2>>>(x, Wd, Wg, bg, gam, bet,
                                                          W1, b1, W2, b2, out, S);
}